// round 12
// baseline (speedup 1.0000x reference)
#include <cuda_runtime.h>
#include <cuda_fp16.h>
#include <cstdint>

#define NB   2048
#define NU   8192
#define ND   256
#define NR   8
#define KTOT (NR*ND + ND)   // 2304

// ---------------- scratch ----------------
__device__ __align__(16) __half g_Ah[(size_t)NB * KTOT];   // 9.4 MB
__device__ __align__(16) __half g_Bh[(size_t)ND * KTOT];   // B[n][k] = W[k][n]

#define GCHUNK 32
#define GITERS (KTOT / GCHUNK)   // 72

// ---------------- helpers ----------------
__device__ __forceinline__ uint32_t smem_u32(const void* p) {
    uint32_t a;
    asm("{ .reg .u64 t; cvta.to.shared.u64 t, %1; cvt.u32.u64 %0, t; }" : "=r"(a) : "l"(p));
    return a;
}
__device__ __forceinline__ void cp16(uint32_t dst, const void* src) {
    asm volatile("cp.async.ca.shared.global [%0], [%1], 16;" :: "r"(dst), "l"(src) : "memory");
}
__device__ __forceinline__ void cp_commit() { asm volatile("cp.async.commit_group;" ::: "memory"); }
__device__ __forceinline__ void cp_wait1()  { asm volatile("cp.async.wait_group 1;" ::: "memory"); }
__device__ __forceinline__ void cp_wait0()  { asm volatile("cp.async.wait_group 0;" ::: "memory"); }
__device__ __forceinline__ void ldm4(uint32_t* r, uint32_t addr) {
    asm volatile("ldmatrix.sync.aligned.m8n8.x4.shared.b16 {%0,%1,%2,%3}, [%4];"
        : "=r"(r[0]), "=r"(r[1]), "=r"(r[2]), "=r"(r[3]) : "r"(addr));
}
__device__ __forceinline__ void mma16816(float* d, const uint32_t* a, const uint32_t* b) {
    asm volatile("mma.sync.aligned.m16n8k16.row.col.f32.f16.f16.f32 "
        "{%0,%1,%2,%3}, {%4,%5,%6,%7}, {%8,%9}, {%0,%1,%2,%3};"
        : "+f"(d[0]), "+f"(d[1]), "+f"(d[2]), "+f"(d[3])
        : "r"(a[0]), "r"(a[1]), "r"(a[2]), "r"(a[3]), "r"(b[0]), "r"(b[1]));
}

// ---------------- K1: build B = W^T (fp16) + self-row gather, merged ----------------
__global__ void prep_kernel(const float* __restrict__ weight,
                            const float* __restrict__ relw,
                            const float* __restrict__ emb,
                            const int* __restrict__ nodes) {
    int blk = blockIdx.x;
    int t = threadIdx.x;
    if (blk < 2304) {
        int j = blk >> 8;        // 0..8
        int n = blk & 255;
        int k = j * 256 + t;
        float v;
        if (k < NR * ND) {
            int r = k >> 8, d = k & 255;
            v = relw[((size_t)r * ND + n) * ND + d];
        } else {
            v = weight[n * ND + (k - NR * ND)];
        }
        g_Bh[(size_t)n * KTOT + k] = __float2half_rn(v);
    } else {
        int w = blk - 2304;
        int b = w * 4 + (t >> 6);
        int c = t & 63;
        int src = nodes[b];
        float4 v = ((const float4*)emb)[(size_t)src * 64 + c];
        size_t base = (size_t)b * KTOT + NR * ND + c * 4;
        __half2* dst = (__half2*)&g_Ah[base];
        dst[0] = __floats2half2_rn(v.x, v.y);
        dst[1] = __floats2half2_rn(v.z, v.w);
    }
}

// ---------------- K2: mask scan (ballot x2 rounds) -> index list -> MLP=4 gather ----------------
#define LIST_CAP 512
__global__ __launch_bounds__(256, 8) void mask_agg_kernel(const float* __restrict__ masks,
                                                          const float* __restrict__ emb,
                                                          const int* __restrict__ unique_idx) {
    __shared__ uint32_t s_bits[256];
    __shared__ uint16_t s_list[LIST_CAP];
    __shared__ int s_wtot[8];
    int t = threadIdx.x;
    int lane = t & 31;
    int w = t >> 5;
    int rb = blockIdx.x;
    int r = rb >> 11;
    int b = rb & 2047;

    const float4* row = (const float4*)(masks + (size_t)rb * NU);
#pragma unroll
    for (int half = 0; half < 2; half++) {
        float4 v[4];
#pragma unroll
        for (int q = 0; q < 4; q++) v[q] = __ldcs(&row[(half * 4 + q) * 256 + t]);
#pragma unroll
        for (int q = 0; q < 4; q++) {
            int c = half * 4 + q;
            uint32_t bx = __ballot_sync(0xffffffffu, v[q].x != 0.0f);
            uint32_t by = __ballot_sync(0xffffffffu, v[q].y != 0.0f);
            uint32_t bz = __ballot_sync(0xffffffffu, v[q].z != 0.0f);
            uint32_t bw = __ballot_sync(0xffffffffu, v[q].w != 0.0f);
            if (lane == 0) {
                int g = c * 8 + w;
                s_bits[g * 4 + 0] = bx;
                s_bits[g * 4 + 1] = by;
                s_bits[g * 4 + 2] = bz;
                s_bits[g * 4 + 3] = bw;
            }
        }
    }
    __syncthreads();

    int Wd = w * 32 + lane;
    uint32_t bits = s_bits[Wd];
    int c = __popc(bits);
    int pre = c;
#pragma unroll
    for (int o = 1; o < 32; o <<= 1) {
        int x = __shfl_up_sync(0xffffffffu, pre, o);
        if (lane >= o) pre += x;
    }
    if (lane == 31) s_wtot[w] = pre;
    int excl = pre - c;
    __syncthreads();

    int base = 0, cnt = 0;
#pragma unroll
    for (int i = 0; i < 8; i++) {
        int x = s_wtot[i];
        if (i < w) base += x;
        cnt += x;
    }
    int pos = base + excl;
    {
        uint32_t bb = bits;
        int comp = Wd & 3;
        int g = Wd >> 2;
        int f4base = (g >> 3) * 256 + (g & 7) * 32;
        while (bb) {
            int j = __ffs(bb) - 1;
            bb &= bb - 1;
            if (pos < LIST_CAP) s_list[pos] = (uint16_t)((f4base + j) * 4 + comp);
            pos++;
        }
    }
    __syncthreads();

    int n = cnt < LIST_CAP ? cnt : LIST_CAP;
    float acc = 0.0f;
    int i = 0;
    for (; i + 4 <= n; i += 4) {
        int u0 = s_list[i], u1 = s_list[i + 1], u2 = s_list[i + 2], u3 = s_list[i + 3];
        int n0 = __ldg(&unique_idx[u0]);
        int n1 = __ldg(&unique_idx[u1]);
        int n2 = __ldg(&unique_idx[u2]);
        int n3 = __ldg(&unique_idx[u3]);
        float v0 = emb[(size_t)n0 * ND + t];
        float v1 = emb[(size_t)n1 * ND + t];
        float v2 = emb[(size_t)n2 * ND + t];
        float v3 = emb[(size_t)n3 * ND + t];
        acc = (((acc + v0) + v1) + v2) + v3;
    }
    for (; i < n; i++) acc += emb[(size_t)__ldg(&unique_idx[s_list[i]]) * ND + t];

    float val = acc * (1.0f / ((float)cnt + 1e-10f));
    g_Ah[(size_t)b * KTOT + r * ND + t] = __float2half_rn(val);
}

// ---------------- K3: single-pass fp16 GEMM + fused ReLU ----------------
// 64x64 tile, 8 warps (2m x 4n), warp tile 32x16, full K=2304 per CTA,
// grid (32, 4) = 128 CTAs (one wave). SMEM/buf: A 5120 + B 5120 = 10240.
#define SM_AH 0
#define SM_BH 5120
#define SM_BUF 10240
#define GSMEM (2 * SM_BUF)

__device__ __forceinline__ void load_chunk(uint32_t sbuf, int m0, int n0, int kc, int tid) {
    {
        int row = tid >> 2;
        int c16 = tid & 3;
        const __half* g = g_Ah + (size_t)(m0 + row) * KTOT + kc + c16 * 8;
        cp16(sbuf + SM_AH + row * 80 + c16 * 16, g);
    }
    {
        int row = tid >> 2;
        int c16 = tid & 3;
        const __half* g = g_Bh + (size_t)(n0 + row) * KTOT + kc + c16 * 8;
        cp16(sbuf + SM_BH + row * 80 + c16 * 16, g);
    }
}

__global__ __launch_bounds__(256, 1) void gemm_direct_kernel(float* __restrict__ out) {
    extern __shared__ char smem[];
    uint32_t sb = smem_u32(smem);
    int tid = threadIdx.x;
    int lane = tid & 31;
    int wid = tid >> 5;
    int wm = wid >> 2;          // 0..1 (32 m each)
    int wn = wid & 3;           // 0..3 (16 n each)
    int m0 = blockIdx.x * 64;
    int n0 = blockIdx.y * 64;

    float acc[2][2][4];
#pragma unroll
    for (int mi = 0; mi < 2; mi++)
#pragma unroll
        for (int nj = 0; nj < 2; nj++)
#pragma unroll
            for (int q = 0; q < 4; q++) acc[mi][nj][q] = 0.0f;

    load_chunk(sb, m0, n0, 0, tid);
    cp_commit();

    int lr = lane & 15;
    int lch = (lane >> 4) * 8;

    for (int it = 0; it < GITERS; it++) {
        uint32_t cbuf = sb + (it & 1) * SM_BUF;
        if (it + 1 < GITERS) {
            load_chunk(sb + ((it + 1) & 1) * SM_BUF, m0, n0, (it + 1) * GCHUNK, tid);
            cp_commit();
            cp_wait1();
        } else {
            cp_wait0();
        }
        __syncthreads();

#pragma unroll
        for (int s = 0; s < 2; s++) {
            uint32_t ah[2][4], bh[2][2];
#pragma unroll
            for (int mi = 0; mi < 2; mi++) {
                uint32_t off = (uint32_t)(wm * 32 + mi * 16 + lr) * 80 + (s * 16 + lch) * 2;
                ldm4(ah[mi], cbuf + SM_AH + off);
            }
            {
                uint32_t off = (uint32_t)(wn * 16 + lr) * 80 + (s * 16 + lch) * 2;
                uint32_t r[4];
                ldm4(r, cbuf + SM_BH + off);
                bh[0][0] = r[0]; bh[0][1] = r[2];
                bh[1][0] = r[1]; bh[1][1] = r[3];
            }
#pragma unroll
            for (int mi = 0; mi < 2; mi++)
#pragma unroll
                for (int nj = 0; nj < 2; nj++)
                    mma16816(acc[mi][nj], ah[mi], bh[nj]);
        }
        __syncthreads();
    }

    // fused ReLU epilogue, direct to output
    int g = lane >> 2;
    int tq = lane & 3;
#pragma unroll
    for (int mi = 0; mi < 2; mi++) {
#pragma unroll
        for (int nj = 0; nj < 2; nj++) {
            int m = m0 + wm * 32 + mi * 16 + g;
            int n = n0 + wn * 16 + nj * 8 + tq * 2;
            float2 v0, v1;
            v0.x = acc[mi][nj][0] > 0.0f ? acc[mi][nj][0] : 0.0f;
            v0.y = acc[mi][nj][1] > 0.0f ? acc[mi][nj][1] : 0.0f;
            v1.x = acc[mi][nj][2] > 0.0f ? acc[mi][nj][2] : 0.0f;
            v1.y = acc[mi][nj][3] > 0.0f ? acc[mi][nj][3] : 0.0f;
            *(float2*)&out[(size_t)m * ND + n] = v0;
            *(float2*)&out[(size_t)(m + 8) * ND + n] = v1;
        }
    }
}

// ---------------- launch (serial, single stream) ----------------
extern "C" void kernel_launch(void* const* d_in, const int* in_sizes, int n_in,
                              void* d_out, int out_size) {
    const int*   nodes  = nullptr;
    const int*   uniq   = nullptr;
    const float* masks  = nullptr;
    const float* emb    = nullptr;
    const float* weight = nullptr;
    const float* relw   = nullptr;

    for (int i = 0; i < n_in; i++) {
        switch (in_sizes[i]) {
            case NB:           nodes  = (const int*)d_in[i];   break;
            case NU:           uniq   = (const int*)d_in[i];   break;
            case NR * NB * NU: masks  = (const float*)d_in[i]; break;
            case 100000 * ND:  emb    = (const float*)d_in[i]; break;
            case ND * ND:      weight = (const float*)d_in[i]; break;
            case NR * ND * ND: relw   = (const float*)d_in[i]; break;
            default: break;
        }
    }
    float* out = (float*)d_out;

    static int smem_set = 0;
    if (!smem_set) {
        cudaFuncSetAttribute(gemm_direct_kernel, cudaFuncAttributeMaxDynamicSharedMemorySize, GSMEM);
        smem_set = 1;
    }

    prep_kernel<<<2304 + NB / 4, 256>>>(weight, relw, emb, nodes);
    mask_agg_kernel<<<NR * NB, 256>>>(masks, emb, uniq);
    gemm_direct_kernel<<<dim3(NB / 64, ND / 64), 256, GSMEM>>>(out);
}

// round 13
// speedup vs baseline: 1.0420x; 1.0420x over previous
#include <cuda_runtime.h>
#include <cuda_fp16.h>
#include <cstdint>

#define NB   2048
#define NU   8192
#define ND   256
#define NR   8
#define KTOT (NR*ND + ND)   // 2304

// ---------------- scratch ----------------
__device__ __align__(16) __half g_Ah[(size_t)NB * KTOT];   // 9.4 MB
__device__ __align__(16) __half g_Bh[(size_t)ND * KTOT];   // B[n][k] = W[k][n]

#define GSPLIT 9
#define GKSPL  (KTOT / GSPLIT)   // 256
#define GCHUNK 32
#define GITERS (GKSPL / GCHUNK)  // 8
__device__ __align__(16) float g_part[(size_t)GSPLIT * NB * ND];
__device__ int g_cnt[64];        // per-(m,n)-tile split completion counters

// ---------------- helpers ----------------
__device__ __forceinline__ uint32_t smem_u32(const void* p) {
    uint32_t a;
    asm("{ .reg .u64 t; cvta.to.shared.u64 t, %1; cvt.u32.u64 %0, t; }" : "=r"(a) : "l"(p));
    return a;
}
__device__ __forceinline__ void cp16(uint32_t dst, const void* src) {
    asm volatile("cp.async.ca.shared.global [%0], [%1], 16;" :: "r"(dst), "l"(src) : "memory");
}
__device__ __forceinline__ void cp_commit() { asm volatile("cp.async.commit_group;" ::: "memory"); }
__device__ __forceinline__ void cp_wait1()  { asm volatile("cp.async.wait_group 1;" ::: "memory"); }
__device__ __forceinline__ void cp_wait0()  { asm volatile("cp.async.wait_group 0;" ::: "memory"); }
__device__ __forceinline__ void ldm4(uint32_t* r, uint32_t addr) {
    asm volatile("ldmatrix.sync.aligned.m8n8.x4.shared.b16 {%0,%1,%2,%3}, [%4];"
        : "=r"(r[0]), "=r"(r[1]), "=r"(r[2]), "=r"(r[3]) : "r"(addr));
}
__device__ __forceinline__ void mma16816(float* d, const uint32_t* a, const uint32_t* b) {
    asm volatile("mma.sync.aligned.m16n8k16.row.col.f32.f16.f16.f32 "
        "{%0,%1,%2,%3}, {%4,%5,%6,%7}, {%8,%9}, {%0,%1,%2,%3};"
        : "+f"(d[0]), "+f"(d[1]), "+f"(d[2]), "+f"(d[3])
        : "r"(a[0]), "r"(a[1]), "r"(a[2]), "r"(a[3]), "r"(b[0]), "r"(b[1]));
}

// ---------------- K1: weight repack + self gather + counter reset ----------------
// blocks [0,256): thread t writes 9 fp16 of B row n=blk
// blocks [256,768): self gather (4 batch rows per block)
__global__ void prep_kernel(const float* __restrict__ weight,
                            const float* __restrict__ relw,
                            const float* __restrict__ emb,
                            const int* __restrict__ nodes) {
    int blk = blockIdx.x;
    int t = threadIdx.x;
    if (blk == 0 && t < 64) g_cnt[t] = 0;
    if (blk < 256) {
        int n = blk;
#pragma unroll
        for (int j = 0; j < 9; j++) {
            float v = (j < 8) ? relw[((size_t)j * ND + n) * ND + t]
                              : weight[n * ND + t];
            g_Bh[(size_t)n * KTOT + j * 256 + t] = __float2half_rn(v);
        }
    } else {
        int w = blk - 256;
        int b = w * 4 + (t >> 6);
        int c = t & 63;
        int src = nodes[b];
        float4 v = ((const float4*)emb)[(size_t)src * 64 + c];
        size_t base = (size_t)b * KTOT + NR * ND + c * 4;
        __half2* dst = (__half2*)&g_Ah[base];
        dst[0] = __floats2half2_rn(v.x, v.y);
        dst[1] = __floats2half2_rn(v.z, v.w);
    }
}

// ---------------- K2: mask scan (ballot x2 rounds) -> index list -> MLP=4 gather ----------------
#define LIST_CAP 512
__global__ __launch_bounds__(256, 8) void mask_agg_kernel(const float* __restrict__ masks,
                                                          const float* __restrict__ emb,
                                                          const int* __restrict__ unique_idx) {
    __shared__ uint32_t s_bits[256];
    __shared__ uint16_t s_list[LIST_CAP];
    __shared__ int s_wtot[8];
    int t = threadIdx.x;
    int lane = t & 31;
    int w = t >> 5;
    int rb = blockIdx.x;
    int r = rb >> 11;
    int b = rb & 2047;

    const float4* row = (const float4*)(masks + (size_t)rb * NU);
#pragma unroll
    for (int half = 0; half < 2; half++) {
        float4 v[4];
#pragma unroll
        for (int q = 0; q < 4; q++) v[q] = __ldcs(&row[(half * 4 + q) * 256 + t]);
#pragma unroll
        for (int q = 0; q < 4; q++) {
            int c = half * 4 + q;
            uint32_t bx = __ballot_sync(0xffffffffu, v[q].x != 0.0f);
            uint32_t by = __ballot_sync(0xffffffffu, v[q].y != 0.0f);
            uint32_t bz = __ballot_sync(0xffffffffu, v[q].z != 0.0f);
            uint32_t bw = __ballot_sync(0xffffffffu, v[q].w != 0.0f);
            if (lane == 0) {
                int g = c * 8 + w;
                s_bits[g * 4 + 0] = bx;
                s_bits[g * 4 + 1] = by;
                s_bits[g * 4 + 2] = bz;
                s_bits[g * 4 + 3] = bw;
            }
        }
    }
    __syncthreads();

    int Wd = w * 32 + lane;
    uint32_t bits = s_bits[Wd];
    int c = __popc(bits);
    int pre = c;
#pragma unroll
    for (int o = 1; o < 32; o <<= 1) {
        int x = __shfl_up_sync(0xffffffffu, pre, o);
        if (lane >= o) pre += x;
    }
    if (lane == 31) s_wtot[w] = pre;
    int excl = pre - c;
    __syncthreads();

    int base = 0, cnt = 0;
#pragma unroll
    for (int i = 0; i < 8; i++) {
        int x = s_wtot[i];
        if (i < w) base += x;
        cnt += x;
    }
    int pos = base + excl;
    {
        uint32_t bb = bits;
        int comp = Wd & 3;
        int g = Wd >> 2;
        int f4base = (g >> 3) * 256 + (g & 7) * 32;
        while (bb) {
            int j = __ffs(bb) - 1;
            bb &= bb - 1;
            if (pos < LIST_CAP) s_list[pos] = (uint16_t)((f4base + j) * 4 + comp);
            pos++;
        }
    }
    __syncthreads();

    int n = cnt < LIST_CAP ? cnt : LIST_CAP;
    float acc = 0.0f;
    int i = 0;
    for (; i + 4 <= n; i += 4) {
        int u0 = s_list[i], u1 = s_list[i + 1], u2 = s_list[i + 2], u3 = s_list[i + 3];
        int n0 = __ldg(&unique_idx[u0]);
        int n1 = __ldg(&unique_idx[u1]);
        int n2 = __ldg(&unique_idx[u2]);
        int n3 = __ldg(&unique_idx[u3]);
        float v0 = emb[(size_t)n0 * ND + t];
        float v1 = emb[(size_t)n1 * ND + t];
        float v2 = emb[(size_t)n2 * ND + t];
        float v3 = emb[(size_t)n3 * ND + t];
        acc = (((acc + v0) + v1) + v2) + v3;
    }
    for (; i < n; i++) acc += emb[(size_t)__ldg(&unique_idx[s_list[i]]) * ND + t];

    float val = acc * (1.0f / ((float)cnt + 1e-10f));
    g_Ah[(size_t)b * KTOT + r * ND + t] = __float2half_rn(val);
}

// ---------------- K3: split-K fp16 GEMM + last-arriver fused reduce/ReLU ----------------
// 128x64 tile, 8 warps (2m x 4n), k-chunk 32. grid (16, 4, GSPLIT) = 576 CTAs.
#define SM_AH 0
#define SM_BH 10240
#define SM_BUF 15360
#define GSMEM (2 * SM_BUF)

__device__ __forceinline__ void load_chunk(uint32_t sbuf, int m0, int n0, int kc, int tid) {
#pragma unroll
    for (int p = 0; p < 2; p++) {
        int o = tid + p * 256;
        int row = o >> 2;
        int c16 = o & 3;
        const __half* g = g_Ah + (size_t)(m0 + row) * KTOT + kc + c16 * 8;
        cp16(sbuf + SM_AH + row * 80 + c16 * 16, g);
    }
    {
        int row = tid >> 2;
        int c16 = tid & 3;
        const __half* g = g_Bh + (size_t)(n0 + row) * KTOT + kc + c16 * 8;
        cp16(sbuf + SM_BH + row * 80 + c16 * 16, g);
    }
}

__global__ __launch_bounds__(256, 4) void gemm_mma_kernel(float* __restrict__ out) {
    extern __shared__ char smem[];
    __shared__ int s_last;
    uint32_t sb = smem_u32(smem);
    int tid = threadIdx.x;
    int lane = tid & 31;
    int wid = tid >> 5;
    int wm = wid >> 2;
    int wn = wid & 3;
    int m0 = blockIdx.x * 128;
    int n0 = blockIdx.y * 64;
    int sp = blockIdx.z;
    int tile = blockIdx.x * 4 + blockIdx.y;   // 0..63
    int kb = sp * GKSPL;

    float acc[4][2][4];
#pragma unroll
    for (int mi = 0; mi < 4; mi++)
#pragma unroll
        for (int nj = 0; nj < 2; nj++)
#pragma unroll
            for (int q = 0; q < 4; q++) acc[mi][nj][q] = 0.0f;

    load_chunk(sb, m0, n0, kb, tid);
    cp_commit();

    int lr = lane & 15;
    int lch = (lane >> 4) * 8;

    for (int it = 0; it < GITERS; it++) {
        uint32_t cbuf = sb + (it & 1) * SM_BUF;
        if (it + 1 < GITERS) {
            load_chunk(sb + ((it + 1) & 1) * SM_BUF, m0, n0, kb + (it + 1) * GCHUNK, tid);
            cp_commit();
            cp_wait1();
        } else {
            cp_wait0();
        }
        __syncthreads();

#pragma unroll
        for (int s = 0; s < 2; s++) {
            uint32_t ah[4][4], bh[2][2];
#pragma unroll
            for (int mi = 0; mi < 4; mi++) {
                uint32_t off = (uint32_t)(wm * 64 + mi * 16 + lr) * 80 + (s * 16 + lch) * 2;
                ldm4(ah[mi], cbuf + SM_AH + off);
            }
            {
                uint32_t off = (uint32_t)(wn * 16 + lr) * 80 + (s * 16 + lch) * 2;
                uint32_t r[4];
                ldm4(r, cbuf + SM_BH + off);
                bh[0][0] = r[0]; bh[0][1] = r[2];
                bh[1][0] = r[1]; bh[1][1] = r[3];
            }
#pragma unroll
            for (int mi = 0; mi < 4; mi++)
#pragma unroll
                for (int nj = 0; nj < 2; nj++)
                    mma16816(acc[mi][nj], ah[mi], bh[nj]);
        }
        __syncthreads();
    }

    // write this split's partial plane
    float* pB = g_part + (size_t)sp * NB * ND;
    int g = lane >> 2;
    int tq = lane & 3;
#pragma unroll
    for (int mi = 0; mi < 4; mi++) {
#pragma unroll
        for (int nj = 0; nj < 2; nj++) {
            int m = m0 + wm * 64 + mi * 16 + g;
            int n = n0 + wn * 16 + nj * 8 + tq * 2;
            float2 v0 = {acc[mi][nj][0], acc[mi][nj][1]};
            float2 v1 = {acc[mi][nj][2], acc[mi][nj][3]};
            *(float2*)&pB[(size_t)m * ND + n] = v0;
            *(float2*)&pB[(size_t)(m + 8) * ND + n] = v1;
        }
    }

    // last-arriver reduce (threadFenceReduction pattern)
    __threadfence();
    __syncthreads();
    if (tid == 0) {
        int old = atomicAdd(&g_cnt[tile], 1);
        s_last = (old == GSPLIT - 1) ? 1 : 0;
    }
    __syncthreads();
    if (!s_last) return;
    __threadfence();

    // this CTA is the 9th: reduce the tile [m0:m0+128][n0:n0+64] over sp=0..8
    // 2048 float4 positions; thread handles 8 (stride 256). Fixed sp order.
#pragma unroll
    for (int p = 0; p < 8; p++) {
        int f = tid + p * 256;
        int rowi = f >> 4;          // 0..127
        int c4 = f & 15;            // 0..15
        size_t off = (size_t)(m0 + rowi) * ND + n0 + c4 * 4;
        const float4* src = (const float4*)(g_part);
        float4 s = *(const float4*)((const char*)src + off * 4);
#pragma unroll
        for (int q = 1; q < GSPLIT; q++) {
            float4 v = *(const float4*)&g_part[(size_t)q * NB * ND + off];
            s.x += v.x; s.y += v.y; s.z += v.z; s.w += v.w;
        }
        s.x = s.x > 0.0f ? s.x : 0.0f;
        s.y = s.y > 0.0f ? s.y : 0.0f;
        s.z = s.z > 0.0f ? s.z : 0.0f;
        s.w = s.w > 0.0f ? s.w : 0.0f;
        *(float4*)&out[off] = s;
    }
}

// ---------------- launch (serial, single stream) ----------------
extern "C" void kernel_launch(void* const* d_in, const int* in_sizes, int n_in,
                              void* d_out, int out_size) {
    const int*   nodes  = nullptr;
    const int*   uniq   = nullptr;
    const float* masks  = nullptr;
    const float* emb    = nullptr;
    const float* weight = nullptr;
    const float* relw   = nullptr;

    for (int i = 0; i < n_in; i++) {
        switch (in_sizes[i]) {
            case NB:           nodes  = (const int*)d_in[i];   break;
            case NU:           uniq   = (const int*)d_in[i];   break;
            case NR * NB * NU: masks  = (const float*)d_in[i]; break;
            case 100000 * ND:  emb    = (const float*)d_in[i]; break;
            case ND * ND:      weight = (const float*)d_in[i]; break;
            case NR * ND * ND: relw   = (const float*)d_in[i]; break;
            default: break;
        }
    }
    float* out = (float*)d_out;

    static int smem_set = 0;
    if (!smem_set) {
        cudaFuncSetAttribute(gemm_mma_kernel, cudaFuncAttributeMaxDynamicSharedMemorySize, GSMEM);
        smem_set = 1;
    }

    prep_kernel<<<768, 256>>>(weight, relw, emb, nodes);
    mask_agg_kernel<<<NR * NB, 256>>>(masks, emb, uniq);
    gemm_mma_kernel<<<dim3(NB / 128, ND / 64, GSPLIT), 256, GSMEM>>>(out);
}

// round 14
// speedup vs baseline: 1.0830x; 1.0393x over previous
#include <cuda_runtime.h>
#include <cuda_fp16.h>
#include <cstdint>

#define NB   2048
#define NU   8192
#define ND   256
#define NR   8
#define KTOT (NR*ND + ND)   // 2304

// ---------------- scratch ----------------
__device__ __align__(16) __half g_Ah[(size_t)NB * KTOT];   // 9.4 MB
__device__ __align__(16) __half g_Bh[(size_t)ND * KTOT];   // B[n][k] = W[k][n]

#define GSPLIT 6
#define GKSPL  (KTOT / GSPLIT)   // 384
#define GCHUNK 32
#define GITERS (GKSPL / GCHUNK)  // 12
__device__ __align__(16) float g_part[(size_t)GSPLIT * NB * ND];   // 12.6 MB

// ---------------- helpers ----------------
__device__ __forceinline__ uint32_t smem_u32(const void* p) {
    uint32_t a;
    asm("{ .reg .u64 t; cvta.to.shared.u64 t, %1; cvt.u32.u64 %0, t; }" : "=r"(a) : "l"(p));
    return a;
}
__device__ __forceinline__ void cp16(uint32_t dst, const void* src) {
    asm volatile("cp.async.ca.shared.global [%0], [%1], 16;" :: "r"(dst), "l"(src) : "memory");
}
__device__ __forceinline__ void cp_commit() { asm volatile("cp.async.commit_group;" ::: "memory"); }
__device__ __forceinline__ void cp_wait1()  { asm volatile("cp.async.wait_group 1;" ::: "memory"); }
__device__ __forceinline__ void cp_wait0()  { asm volatile("cp.async.wait_group 0;" ::: "memory"); }
__device__ __forceinline__ void ldm4(uint32_t* r, uint32_t addr) {
    asm volatile("ldmatrix.sync.aligned.m8n8.x4.shared.b16 {%0,%1,%2,%3}, [%4];"
        : "=r"(r[0]), "=r"(r[1]), "=r"(r[2]), "=r"(r[3]) : "r"(addr));
}
__device__ __forceinline__ void mma16816(float* d, const uint32_t* a, const uint32_t* b) {
    asm volatile("mma.sync.aligned.m16n8k16.row.col.f32.f16.f16.f32 "
        "{%0,%1,%2,%3}, {%4,%5,%6,%7}, {%8,%9}, {%0,%1,%2,%3};"
        : "+f"(d[0]), "+f"(d[1]), "+f"(d[2]), "+f"(d[3])
        : "r"(a[0]), "r"(a[1]), "r"(a[2]), "r"(a[3]), "r"(b[0]), "r"(b[1]));
}

// ---------------- K1: combo — prep (blocks 0..767) + mask agg (blocks 768+) ----------------
// prep blocks [0,256): thread t writes 9 fp16 of B row n=blk
// prep blocks [256,768): self gather (4 batch rows per block)
// mask blocks: one (r,b) row each — ballot scan -> list -> MLP=4 gather
#define LIST_CAP 512
#define PREP_BLKS 768
__global__ __launch_bounds__(256, 8) void combo_kernel(const float* __restrict__ masks,
                                                       const float* __restrict__ emb,
                                                       const int* __restrict__ unique_idx,
                                                       const int* __restrict__ nodes,
                                                       const float* __restrict__ weight,
                                                       const float* __restrict__ relw) {
    int blk = blockIdx.x;
    int t = threadIdx.x;

    if (blk < PREP_BLKS) {
        if (blk < 256) {
            int n = blk;
#pragma unroll
            for (int j = 0; j < 9; j++) {
                float v = (j < 8) ? relw[((size_t)j * ND + n) * ND + t]
                                  : weight[n * ND + t];
                g_Bh[(size_t)n * KTOT + j * 256 + t] = __float2half_rn(v);
            }
        } else {
            int w = blk - 256;
            int b = w * 4 + (t >> 6);
            int c = t & 63;
            int src = nodes[b];
            float4 v = ((const float4*)emb)[(size_t)src * 64 + c];
            size_t base = (size_t)b * KTOT + NR * ND + c * 4;
            __half2* dst = (__half2*)&g_Ah[base];
            dst[0] = __floats2half2_rn(v.x, v.y);
            dst[1] = __floats2half2_rn(v.z, v.w);
        }
        return;
    }

    __shared__ uint32_t s_bits[256];
    __shared__ uint16_t s_list[LIST_CAP];
    __shared__ int s_wtot[8];
    int lane = t & 31;
    int w = t >> 5;
    int rb = blk - PREP_BLKS;
    int r = rb >> 11;
    int b = rb & 2047;

    const float4* row = (const float4*)(masks + (size_t)rb * NU);
#pragma unroll
    for (int half = 0; half < 2; half++) {
        float4 v[4];
#pragma unroll
        for (int q = 0; q < 4; q++) v[q] = __ldcs(&row[(half * 4 + q) * 256 + t]);
#pragma unroll
        for (int q = 0; q < 4; q++) {
            int c = half * 4 + q;
            uint32_t bx = __ballot_sync(0xffffffffu, v[q].x != 0.0f);
            uint32_t by = __ballot_sync(0xffffffffu, v[q].y != 0.0f);
            uint32_t bz = __ballot_sync(0xffffffffu, v[q].z != 0.0f);
            uint32_t bw = __ballot_sync(0xffffffffu, v[q].w != 0.0f);
            if (lane == 0) {
                int g = c * 8 + w;
                s_bits[g * 4 + 0] = bx;
                s_bits[g * 4 + 1] = by;
                s_bits[g * 4 + 2] = bz;
                s_bits[g * 4 + 3] = bw;
            }
        }
    }
    __syncthreads();

    int Wd = w * 32 + lane;
    uint32_t bits = s_bits[Wd];
    int c = __popc(bits);
    int pre = c;
#pragma unroll
    for (int o = 1; o < 32; o <<= 1) {
        int x = __shfl_up_sync(0xffffffffu, pre, o);
        if (lane >= o) pre += x;
    }
    if (lane == 31) s_wtot[w] = pre;
    int excl = pre - c;
    __syncthreads();

    int base = 0, cnt = 0;
#pragma unroll
    for (int i = 0; i < 8; i++) {
        int x = s_wtot[i];
        if (i < w) base += x;
        cnt += x;
    }
    int pos = base + excl;
    {
        uint32_t bb = bits;
        int comp = Wd & 3;
        int g = Wd >> 2;
        int f4base = (g >> 3) * 256 + (g & 7) * 32;
        while (bb) {
            int j = __ffs(bb) - 1;
            bb &= bb - 1;
            if (pos < LIST_CAP) s_list[pos] = (uint16_t)((f4base + j) * 4 + comp);
            pos++;
        }
    }
    __syncthreads();

    int n = cnt < LIST_CAP ? cnt : LIST_CAP;
    float acc = 0.0f;
    int i = 0;
    for (; i + 4 <= n; i += 4) {
        int u0 = s_list[i], u1 = s_list[i + 1], u2 = s_list[i + 2], u3 = s_list[i + 3];
        int n0 = __ldg(&unique_idx[u0]);
        int n1 = __ldg(&unique_idx[u1]);
        int n2 = __ldg(&unique_idx[u2]);
        int n3 = __ldg(&unique_idx[u3]);
        float v0 = emb[(size_t)n0 * ND + t];
        float v1 = emb[(size_t)n1 * ND + t];
        float v2 = emb[(size_t)n2 * ND + t];
        float v3 = emb[(size_t)n3 * ND + t];
        acc = (((acc + v0) + v1) + v2) + v3;
    }
    for (; i < n; i++) acc += emb[(size_t)__ldg(&unique_idx[s_list[i]]) * ND + t];

    float val = acc * (1.0f / ((float)cnt + 1e-10f));
    g_Ah[(size_t)b * KTOT + r * ND + t] = __float2half_rn(val);
}

// ---------------- K2: split-K fp16 GEMM (128x64 tile, GSPLIT=6) ----------------
#define SM_AH 0
#define SM_BH 10240
#define SM_BUF 15360
#define GSMEM (2 * SM_BUF)

__device__ __forceinline__ void load_chunk(uint32_t sbuf, int m0, int n0, int kc, int tid) {
#pragma unroll
    for (int p = 0; p < 2; p++) {
        int o = tid + p * 256;
        int row = o >> 2;
        int c16 = o & 3;
        const __half* g = g_Ah + (size_t)(m0 + row) * KTOT + kc + c16 * 8;
        cp16(sbuf + SM_AH + row * 80 + c16 * 16, g);
    }
    {
        int row = tid >> 2;
        int c16 = tid & 3;
        const __half* g = g_Bh + (size_t)(n0 + row) * KTOT + kc + c16 * 8;
        cp16(sbuf + SM_BH + row * 80 + c16 * 16, g);
    }
}

__global__ __launch_bounds__(256, 4) void gemm_mma_kernel() {
    extern __shared__ char smem[];
    uint32_t sb = smem_u32(smem);
    int tid = threadIdx.x;
    int lane = tid & 31;
    int wid = tid >> 5;
    int wm = wid >> 2;          // 0..1
    int wn = wid & 3;           // 0..3
    int m0 = blockIdx.x * 128;
    int n0 = blockIdx.y * 64;
    int sp = blockIdx.z;
    int kb = sp * GKSPL;

    float acc[4][2][4];
#pragma unroll
    for (int mi = 0; mi < 4; mi++)
#pragma unroll
        for (int nj = 0; nj < 2; nj++)
#pragma unroll
            for (int q = 0; q < 4; q++) acc[mi][nj][q] = 0.0f;

    load_chunk(sb, m0, n0, kb, tid);
    cp_commit();

    int lr = lane & 15;
    int lch = (lane >> 4) * 8;

    for (int it = 0; it < GITERS; it++) {
        uint32_t cbuf = sb + (it & 1) * SM_BUF;
        if (it + 1 < GITERS) {
            load_chunk(sb + ((it + 1) & 1) * SM_BUF, m0, n0, kb + (it + 1) * GCHUNK, tid);
            cp_commit();
            cp_wait1();
        } else {
            cp_wait0();
        }
        __syncthreads();

#pragma unroll
        for (int s = 0; s < 2; s++) {
            uint32_t ah[4][4], bh[2][2];
#pragma unroll
            for (int mi = 0; mi < 4; mi++) {
                uint32_t off = (uint32_t)(wm * 64 + mi * 16 + lr) * 80 + (s * 16 + lch) * 2;
                ldm4(ah[mi], cbuf + SM_AH + off);
            }
            {
                uint32_t off = (uint32_t)(wn * 16 + lr) * 80 + (s * 16 + lch) * 2;
                uint32_t r[4];
                ldm4(r, cbuf + SM_BH + off);
                bh[0][0] = r[0]; bh[0][1] = r[2];
                bh[1][0] = r[1]; bh[1][1] = r[3];
            }
#pragma unroll
            for (int mi = 0; mi < 4; mi++)
#pragma unroll
                for (int nj = 0; nj < 2; nj++)
                    mma16816(acc[mi][nj], ah[mi], bh[nj]);
        }
        __syncthreads();
    }

    float* pB = g_part + (size_t)sp * NB * ND;
    int g = lane >> 2;
    int tq = lane & 3;
#pragma unroll
    for (int mi = 0; mi < 4; mi++) {
#pragma unroll
        for (int nj = 0; nj < 2; nj++) {
            int m = m0 + wm * 64 + mi * 16 + g;
            int n = n0 + wn * 16 + nj * 8 + tq * 2;
            float2 v0 = {acc[mi][nj][0], acc[mi][nj][1]};
            float2 v1 = {acc[mi][nj][2], acc[mi][nj][3]};
            *(float2*)&pB[(size_t)m * ND + n] = v0;
            *(float2*)&pB[(size_t)(m + 8) * ND + n] = v1;
        }
    }
}

// ---------------- K3: deterministic reduce + ReLU (6 planes) ----------------
__global__ void reduce_relu_kernel(float* __restrict__ out) {
    int idx = blockIdx.x * 256 + threadIdx.x;
    const float4* p = (const float4*)g_part;
    float4 v[GSPLIT];
#pragma unroll
    for (int sp = 0; sp < GSPLIT; sp++)            // all loads issued upfront
        v[sp] = p[(size_t)sp * (NB * ND / 4) + idx];
    float4 s = v[0];
#pragma unroll
    for (int sp = 1; sp < GSPLIT; sp++) {
        s.x += v[sp].x; s.y += v[sp].y; s.z += v[sp].z; s.w += v[sp].w;
    }
    s.x = s.x > 0.0f ? s.x : 0.0f;
    s.y = s.y > 0.0f ? s.y : 0.0f;
    s.z = s.z > 0.0f ? s.z : 0.0f;
    s.w = s.w > 0.0f ? s.w : 0.0f;
    ((float4*)out)[idx] = s;
}

// ---------------- launch (serial, single stream) ----------------
extern "C" void kernel_launch(void* const* d_in, const int* in_sizes, int n_in,
                              void* d_out, int out_size) {
    const int*   nodes  = nullptr;
    const int*   uniq   = nullptr;
    const float* masks  = nullptr;
    const float* emb    = nullptr;
    const float* weight = nullptr;
    const float* relw   = nullptr;

    for (int i = 0; i < n_in; i++) {
        switch (in_sizes[i]) {
            case NB:           nodes  = (const int*)d_in[i];   break;
            case NU:           uniq   = (const int*)d_in[i];   break;
            case NR * NB * NU: masks  = (const float*)d_in[i]; break;
            case 100000 * ND:  emb    = (const float*)d_in[i]; break;
            case ND * ND:      weight = (const float*)d_in[i]; break;
            case NR * ND * ND: relw   = (const float*)d_in[i]; break;
            default: break;
        }
    }
    float* out = (float*)d_out;

    static int smem_set = 0;
    if (!smem_set) {
        cudaFuncSetAttribute(gemm_mma_kernel, cudaFuncAttributeMaxDynamicSharedMemorySize, GSMEM);
        smem_set = 1;
    }

    combo_kernel<<<PREP_BLKS + NR * NB, 256>>>(masks, emb, uniq, nodes, weight, relw);
    gemm_mma_kernel<<<dim3(NB / 128, ND / 64, GSPLIT), 256, GSMEM>>>();
    reduce_relu_kernel<<<NB * ND / 4 / 256, 256>>>(out);
}

// round 15
// speedup vs baseline: 1.0863x; 1.0031x over previous
#include <cuda_runtime.h>
#include <cuda_fp16.h>
#include <cstdint>

#define NB   2048
#define NU   8192
#define ND   256
#define NR   8
#define KTOT (NR*ND + ND)   // 2304

// ---------------- scratch ----------------
__device__ __align__(16) __half g_Ah[(size_t)NB * KTOT];   // 9.4 MB
__device__ __align__(16) __half g_Bh[(size_t)ND * KTOT];   // B[n][k] = W[k][n]

#define GSPLIT 6
#define GKSPL  (KTOT / GSPLIT)   // 384
#define GCHUNK 32
#define GITERS (GKSPL / GCHUNK)  // 12
__device__ __align__(16) float g_part[(size_t)GSPLIT * NB * ND];   // 12.6 MB

// ---------------- helpers ----------------
__device__ __forceinline__ uint32_t smem_u32(const void* p) {
    uint32_t a;
    asm("{ .reg .u64 t; cvta.to.shared.u64 t, %1; cvt.u32.u64 %0, t; }" : "=r"(a) : "l"(p));
    return a;
}
__device__ __forceinline__ void cp16(uint32_t dst, const void* src) {
    asm volatile("cp.async.ca.shared.global [%0], [%1], 16;" :: "r"(dst), "l"(src) : "memory");
}
__device__ __forceinline__ void cp_commit() { asm volatile("cp.async.commit_group;" ::: "memory"); }
__device__ __forceinline__ void cp_wait1()  { asm volatile("cp.async.wait_group 1;" ::: "memory"); }
__device__ __forceinline__ void cp_wait0()  { asm volatile("cp.async.wait_group 0;" ::: "memory"); }
__device__ __forceinline__ void ldm4(uint32_t* r, uint32_t addr) {
    asm volatile("ldmatrix.sync.aligned.m8n8.x4.shared.b16 {%0,%1,%2,%3}, [%4];"
        : "=r"(r[0]), "=r"(r[1]), "=r"(r[2]), "=r"(r[3]) : "r"(addr));
}
__device__ __forceinline__ void mma16816(float* d, const uint32_t* a, const uint32_t* b) {
    asm volatile("mma.sync.aligned.m16n8k16.row.col.f32.f16.f16.f32 "
        "{%0,%1,%2,%3}, {%4,%5,%6,%7}, {%8,%9}, {%0,%1,%2,%3};"
        : "+f"(d[0]), "+f"(d[1]), "+f"(d[2]), "+f"(d[3])
        : "r"(a[0]), "r"(a[1]), "r"(a[2]), "r"(a[3]), "r"(b[0]), "r"(b[1]));
}

// ---------------- K1: combo — mask agg (blocks 0..16383) + prep (blocks 16384+) ----------------
// mask blocks: one (r,b) row each — ballot scan -> list -> MLP=4 gather
// prep blocks [MASK_BLKS, MASK_BLKS+256): thread t writes 9 fp16 of B row n
// prep blocks [+256, +768): self gather (4 batch rows per block)
#define LIST_CAP 512
#define MASK_BLKS (NR * NB)
__global__ __launch_bounds__(256, 8) void combo_kernel(const float* __restrict__ masks,
                                                       const float* __restrict__ emb,
                                                       const int* __restrict__ unique_idx,
                                                       const int* __restrict__ nodes,
                                                       const float* __restrict__ weight,
                                                       const float* __restrict__ relw) {
    int blk = blockIdx.x;
    int t = threadIdx.x;

    if (blk >= MASK_BLKS) {
        int pb = blk - MASK_BLKS;
        if (pb < 256) {
            int n = pb;
#pragma unroll
            for (int j = 0; j < 9; j++) {
                float v = (j < 8) ? relw[((size_t)j * ND + n) * ND + t]
                                  : weight[n * ND + t];
                g_Bh[(size_t)n * KTOT + j * 256 + t] = __float2half_rn(v);
            }
        } else {
            int w = pb - 256;
            int b = w * 4 + (t >> 6);
            int c = t & 63;
            int src = nodes[b];
            float4 v = ((const float4*)emb)[(size_t)src * 64 + c];
            size_t base = (size_t)b * KTOT + NR * ND + c * 4;
            __half2* dst = (__half2*)&g_Ah[base];
            dst[0] = __floats2half2_rn(v.x, v.y);
            dst[1] = __floats2half2_rn(v.z, v.w);
        }
        return;
    }

    __shared__ uint32_t s_bits[256];
    __shared__ uint16_t s_list[LIST_CAP];
    __shared__ int s_wtot[8];
    int lane = t & 31;
    int w = t >> 5;
    int rb = blk;
    int r = rb >> 11;
    int b = rb & 2047;

    const float4* row = (const float4*)(masks + (size_t)rb * NU);
#pragma unroll
    for (int half = 0; half < 2; half++) {
        float4 v[4];
#pragma unroll
        for (int q = 0; q < 4; q++) v[q] = __ldcs(&row[(half * 4 + q) * 256 + t]);
#pragma unroll
        for (int q = 0; q < 4; q++) {
            int c = half * 4 + q;
            uint32_t bx = __ballot_sync(0xffffffffu, v[q].x != 0.0f);
            uint32_t by = __ballot_sync(0xffffffffu, v[q].y != 0.0f);
            uint32_t bz = __ballot_sync(0xffffffffu, v[q].z != 0.0f);
            uint32_t bw = __ballot_sync(0xffffffffu, v[q].w != 0.0f);
            if (lane == 0) {
                int g = c * 8 + w;
                s_bits[g * 4 + 0] = bx;
                s_bits[g * 4 + 1] = by;
                s_bits[g * 4 + 2] = bz;
                s_bits[g * 4 + 3] = bw;
            }
        }
    }
    __syncthreads();

    int Wd = w * 32 + lane;
    uint32_t bits = s_bits[Wd];
    int c = __popc(bits);
    int pre = c;
#pragma unroll
    for (int o = 1; o < 32; o <<= 1) {
        int x = __shfl_up_sync(0xffffffffu, pre, o);
        if (lane >= o) pre += x;
    }
    if (lane == 31) s_wtot[w] = pre;
    int excl = pre - c;
    __syncthreads();

    int base = 0, cnt = 0;
#pragma unroll
    for (int i = 0; i < 8; i++) {
        int x = s_wtot[i];
        if (i < w) base += x;
        cnt += x;
    }
    int pos = base + excl;
    {
        uint32_t bb = bits;
        int comp = Wd & 3;
        int g = Wd >> 2;
        int f4base = (g >> 3) * 256 + (g & 7) * 32;
        while (bb) {
            int j = __ffs(bb) - 1;
            bb &= bb - 1;
            if (pos < LIST_CAP) s_list[pos] = (uint16_t)((f4base + j) * 4 + comp);
            pos++;
        }
    }
    __syncthreads();

    int n = cnt < LIST_CAP ? cnt : LIST_CAP;
    float acc = 0.0f;
    int i = 0;
    for (; i + 4 <= n; i += 4) {
        int u0 = s_list[i], u1 = s_list[i + 1], u2 = s_list[i + 2], u3 = s_list[i + 3];
        int n0 = __ldg(&unique_idx[u0]);
        int n1 = __ldg(&unique_idx[u1]);
        int n2 = __ldg(&unique_idx[u2]);
        int n3 = __ldg(&unique_idx[u3]);
        float v0 = emb[(size_t)n0 * ND + t];
        float v1 = emb[(size_t)n1 * ND + t];
        float v2 = emb[(size_t)n2 * ND + t];
        float v3 = emb[(size_t)n3 * ND + t];
        acc = (((acc + v0) + v1) + v2) + v3;
    }
    for (; i < n; i++) acc += emb[(size_t)__ldg(&unique_idx[s_list[i]]) * ND + t];

    float val = acc * (1.0f / ((float)cnt + 1e-10f));
    g_Ah[(size_t)b * KTOT + r * ND + t] = __float2half_rn(val);
}

// ---------------- K2: split-K fp16 GEMM (128x64 tile, GSPLIT=6) ----------------
#define SM_AH 0
#define SM_BH 10240
#define SM_BUF 15360
#define GSMEM (2 * SM_BUF)

__device__ __forceinline__ void load_chunk(uint32_t sbuf, int m0, int n0, int kc, int tid) {
#pragma unroll
    for (int p = 0; p < 2; p++) {
        int o = tid + p * 256;
        int row = o >> 2;
        int c16 = o & 3;
        const __half* g = g_Ah + (size_t)(m0 + row) * KTOT + kc + c16 * 8;
        cp16(sbuf + SM_AH + row * 80 + c16 * 16, g);
    }
    {
        int row = tid >> 2;
        int c16 = tid & 3;
        const __half* g = g_Bh + (size_t)(n0 + row) * KTOT + kc + c16 * 8;
        cp16(sbuf + SM_BH + row * 80 + c16 * 16, g);
    }
}

__global__ __launch_bounds__(256, 3) void gemm_mma_kernel() {
    extern __shared__ char smem[];
    uint32_t sb = smem_u32(smem);
    int tid = threadIdx.x;
    int lane = tid & 31;
    int wid = tid >> 5;
    int wm = wid >> 2;          // 0..1
    int wn = wid & 3;           // 0..3
    int m0 = blockIdx.x * 128;
    int n0 = blockIdx.y * 64;
    int sp = blockIdx.z;
    int kb = sp * GKSPL;

    float acc[4][2][4];
#pragma unroll
    for (int mi = 0; mi < 4; mi++)
#pragma unroll
        for (int nj = 0; nj < 2; nj++)
#pragma unroll
            for (int q = 0; q < 4; q++) acc[mi][nj][q] = 0.0f;

    load_chunk(sb, m0, n0, kb, tid);
    cp_commit();

    int lr = lane & 15;
    int lch = (lane >> 4) * 8;

    for (int it = 0; it < GITERS; it++) {
        uint32_t cbuf = sb + (it & 1) * SM_BUF;
        if (it + 1 < GITERS) {
            load_chunk(sb + ((it + 1) & 1) * SM_BUF, m0, n0, kb + (it + 1) * GCHUNK, tid);
            cp_commit();
            cp_wait1();
        } else {
            cp_wait0();
        }
        __syncthreads();

#pragma unroll
        for (int s = 0; s < 2; s++) {
            uint32_t ah[4][4], bh[2][2];
#pragma unroll
            for (int mi = 0; mi < 4; mi++) {
                uint32_t off = (uint32_t)(wm * 64 + mi * 16 + lr) * 80 + (s * 16 + lch) * 2;
                ldm4(ah[mi], cbuf + SM_AH + off);
            }
            {
                uint32_t off = (uint32_t)(wn * 16 + lr) * 80 + (s * 16 + lch) * 2;
                uint32_t r[4];
                ldm4(r, cbuf + SM_BH + off);
                bh[0][0] = r[0]; bh[0][1] = r[2];
                bh[1][0] = r[1]; bh[1][1] = r[3];
            }
#pragma unroll
            for (int mi = 0; mi < 4; mi++)
#pragma unroll
                for (int nj = 0; nj < 2; nj++)
                    mma16816(acc[mi][nj], ah[mi], bh[nj]);
        }
        __syncthreads();
    }

    float* pB = g_part + (size_t)sp * NB * ND;
    int g = lane >> 2;
    int tq = lane & 3;
#pragma unroll
    for (int mi = 0; mi < 4; mi++) {
#pragma unroll
        for (int nj = 0; nj < 2; nj++) {
            int m = m0 + wm * 64 + mi * 16 + g;
            int n = n0 + wn * 16 + nj * 8 + tq * 2;
            float2 v0 = {acc[mi][nj][0], acc[mi][nj][1]};
            float2 v1 = {acc[mi][nj][2], acc[mi][nj][3]};
            *(float2*)&pB[(size_t)m * ND + n] = v0;
            *(float2*)&pB[(size_t)(m + 8) * ND + n] = v1;
        }
    }
}

// ---------------- K3: deterministic reduce + ReLU (float2 granularity, 2x warps) ----------------
__global__ void reduce_relu_kernel(float* __restrict__ out) {
    int idx = blockIdx.x * 256 + threadIdx.x;      // float2 index, 262144 total
    const float2* p = (const float2*)g_part;
    float2 v[GSPLIT];
#pragma unroll
    for (int sp = 0; sp < GSPLIT; sp++)
        v[sp] = p[(size_t)sp * (NB * ND / 2) + idx];
    float2 s = v[0];
#pragma unroll
    for (int sp = 1; sp < GSPLIT; sp++) { s.x += v[sp].x; s.y += v[sp].y; }
    s.x = s.x > 0.0f ? s.x : 0.0f;
    s.y = s.y > 0.0f ? s.y : 0.0f;
    ((float2*)out)[idx] = s;
}

// ---------------- launch (serial, single stream) ----------------
extern "C" void kernel_launch(void* const* d_in, const int* in_sizes, int n_in,
                              void* d_out, int out_size) {
    const int*   nodes  = nullptr;
    const int*   uniq   = nullptr;
    const float* masks  = nullptr;
    const float* emb    = nullptr;
    const float* weight = nullptr;
    const float* relw   = nullptr;

    for (int i = 0; i < n_in; i++) {
        switch (in_sizes[i]) {
            case NB:           nodes  = (const int*)d_in[i];   break;
            case NU:           uniq   = (const int*)d_in[i];   break;
            case NR * NB * NU: masks  = (const float*)d_in[i]; break;
            case 100000 * ND:  emb    = (const float*)d_in[i]; break;
            case ND * ND:      weight = (const float*)d_in[i]; break;
            case NR * ND * ND: relw   = (const float*)d_in[i]; break;
            default: break;
        }
    }
    float* out = (float*)d_out;

    static int smem_set = 0;
    if (!smem_set) {
        cudaFuncSetAttribute(gemm_mma_kernel, cudaFuncAttributeMaxDynamicSharedMemorySize, GSMEM);
        smem_set = 1;
    }

    combo_kernel<<<MASK_BLKS + 768, 256>>>(masks, emb, uniq, nodes, weight, relw);
    gemm_mma_kernel<<<dim3(NB / 128, ND / 64, GSPLIT), 256, GSMEM>>>();
    reduce_relu_kernel<<<NB * ND / 2 / 256, 256>>>(out);
}

// round 16
// speedup vs baseline: 1.0933x; 1.0065x over previous
#include <cuda_runtime.h>
#include <cuda_fp16.h>
#include <cstdint>

#define NB   2048
#define NU   8192
#define ND   256
#define NR   8
#define KTOT (NR*ND + ND)   // 2304

// ---------------- scratch ----------------
__device__ __align__(16) __half g_Ah[(size_t)NB * KTOT];   // 9.4 MB
__device__ __align__(16) __half g_Bh[(size_t)ND * KTOT];   // B[n][k] = W[k][n]

#define GSPLIT 6
#define GKSPL  (KTOT / GSPLIT)   // 384
#define GCHUNK 32
#define GITERS (GKSPL / GCHUNK)  // 12
__device__ __align__(16) float g_part[(size_t)GSPLIT * NB * ND];   // 12.6 MB

// ---------------- helpers ----------------
__device__ __forceinline__ uint32_t smem_u32(const void* p) {
    uint32_t a;
    asm("{ .reg .u64 t; cvta.to.shared.u64 t, %1; cvt.u32.u64 %0, t; }" : "=r"(a) : "l"(p));
    return a;
}
__device__ __forceinline__ void cp16(uint32_t dst, const void* src) {
    asm volatile("cp.async.ca.shared.global [%0], [%1], 16;" :: "r"(dst), "l"(src) : "memory");
}
__device__ __forceinline__ void cp_commit() { asm volatile("cp.async.commit_group;" ::: "memory"); }
__device__ __forceinline__ void cp_wait1()  { asm volatile("cp.async.wait_group 1;" ::: "memory"); }
__device__ __forceinline__ void cp_wait0()  { asm volatile("cp.async.wait_group 0;" ::: "memory"); }
__device__ __forceinline__ void ldm4(uint32_t* r, uint32_t addr) {
    asm volatile("ldmatrix.sync.aligned.m8n8.x4.shared.b16 {%0,%1,%2,%3}, [%4];"
        : "=r"(r[0]), "=r"(r[1]), "=r"(r[2]), "=r"(r[3]) : "r"(addr));
}
__device__ __forceinline__ void mma16816(float* d, const uint32_t* a, const uint32_t* b) {
    asm volatile("mma.sync.aligned.m16n8k16.row.col.f32.f16.f16.f32 "
        "{%0,%1,%2,%3}, {%4,%5,%6,%7}, {%8,%9}, {%0,%1,%2,%3};"
        : "+f"(d[0]), "+f"(d[1]), "+f"(d[2]), "+f"(d[3])
        : "r"(a[0]), "r"(a[1]), "r"(a[2]), "r"(a[3]), "r"(b[0]), "r"(b[1]));
}

// ---------------- K1: combo — mask agg (blocks 0..16383) + prep (blocks 16384+) ----------------
#define LIST_CAP 512
#define MASK_BLKS (NR * NB)
__global__ __launch_bounds__(256, 8) void combo_kernel(const float* __restrict__ masks,
                                                       const float* __restrict__ emb,
                                                       const int* __restrict__ unique_idx,
                                                       const int* __restrict__ nodes,
                                                       const float* __restrict__ weight,
                                                       const float* __restrict__ relw) {
    int blk = blockIdx.x;
    int t = threadIdx.x;

    if (blk >= MASK_BLKS) {
        int pb = blk - MASK_BLKS;
        if (pb < 256) {
            int n = pb;
#pragma unroll
            for (int j = 0; j < 9; j++) {
                float v = (j < 8) ? relw[((size_t)j * ND + n) * ND + t]
                                  : weight[n * ND + t];
                g_Bh[(size_t)n * KTOT + j * 256 + t] = __float2half_rn(v);
            }
        } else {
            int w = pb - 256;
            int b = w * 4 + (t >> 6);
            int c = t & 63;
            int src = nodes[b];
            float4 v = ((const float4*)emb)[(size_t)src * 64 + c];
            size_t base = (size_t)b * KTOT + NR * ND + c * 4;
            __half2* dst = (__half2*)&g_Ah[base];
            dst[0] = __floats2half2_rn(v.x, v.y);
            dst[1] = __floats2half2_rn(v.z, v.w);
        }
        return;
    }

    __shared__ uint32_t s_bits[256];
    __shared__ uint16_t s_list[LIST_CAP];
    __shared__ int s_wtot[8];
    int lane = t & 31;
    int w = t >> 5;
    int rb = blk;
    int r = rb >> 11;
    int b = rb & 2047;

    const float4* row = (const float4*)(masks + (size_t)rb * NU);
#pragma unroll
    for (int half = 0; half < 2; half++) {
        float4 v[4];
#pragma unroll
        for (int q = 0; q < 4; q++) v[q] = __ldcs(&row[(half * 4 + q) * 256 + t]);
#pragma unroll
        for (int q = 0; q < 4; q++) {
            int c = half * 4 + q;
            uint32_t bx = __ballot_sync(0xffffffffu, v[q].x != 0.0f);
            uint32_t by = __ballot_sync(0xffffffffu, v[q].y != 0.0f);
            uint32_t bz = __ballot_sync(0xffffffffu, v[q].z != 0.0f);
            uint32_t bw = __ballot_sync(0xffffffffu, v[q].w != 0.0f);
            if (lane == 0) {
                int g = c * 8 + w;
                s_bits[g * 4 + 0] = bx;
                s_bits[g * 4 + 1] = by;
                s_bits[g * 4 + 2] = bz;
                s_bits[g * 4 + 3] = bw;
            }
        }
    }
    __syncthreads();

    int Wd = w * 32 + lane;
    uint32_t bits = s_bits[Wd];
    int c = __popc(bits);
    int pre = c;
#pragma unroll
    for (int o = 1; o < 32; o <<= 1) {
        int x = __shfl_up_sync(0xffffffffu, pre, o);
        if (lane >= o) pre += x;
    }
    if (lane == 31) s_wtot[w] = pre;
    int excl = pre - c;
    __syncthreads();

    int base = 0, cnt = 0;
#pragma unroll
    for (int i = 0; i < 8; i++) {
        int x = s_wtot[i];
        if (i < w) base += x;
        cnt += x;
    }
    int pos = base + excl;
    {
        uint32_t bb = bits;
        int comp = Wd & 3;
        int g = Wd >> 2;
        int f4base = (g >> 3) * 256 + (g & 7) * 32;
        while (bb) {
            int j = __ffs(bb) - 1;
            bb &= bb - 1;
            if (pos < LIST_CAP) s_list[pos] = (uint16_t)((f4base + j) * 4 + comp);
            pos++;
        }
    }
    __syncthreads();

    int n = cnt < LIST_CAP ? cnt : LIST_CAP;
    float acc = 0.0f;
    int i = 0;
    for (; i + 4 <= n; i += 4) {
        int u0 = s_list[i], u1 = s_list[i + 1], u2 = s_list[i + 2], u3 = s_list[i + 3];
        int n0 = __ldg(&unique_idx[u0]);
        int n1 = __ldg(&unique_idx[u1]);
        int n2 = __ldg(&unique_idx[u2]);
        int n3 = __ldg(&unique_idx[u3]);
        float v0 = emb[(size_t)n0 * ND + t];
        float v1 = emb[(size_t)n1 * ND + t];
        float v2 = emb[(size_t)n2 * ND + t];
        float v3 = emb[(size_t)n3 * ND + t];
        acc = (((acc + v0) + v1) + v2) + v3;
    }
    for (; i < n; i++) acc += emb[(size_t)__ldg(&unique_idx[s_list[i]]) * ND + t];

    float val = acc * (1.0f / ((float)cnt + 1e-10f));
    g_Ah[(size_t)b * KTOT + r * ND + t] = __float2half_rn(val);
}

// ---------------- K2: split-K fp16 GEMM, 3-stage cp.async, 1 sync/iter ----------------
#define SM_AH 0
#define SM_BH 10240
#define SM_BUF 15360
#define NSTAGE 3
#define GSMEM (NSTAGE * SM_BUF)

__device__ __forceinline__ void load_chunk(uint32_t sbuf, int m0, int n0, int kc, int tid) {
#pragma unroll
    for (int p = 0; p < 2; p++) {
        int o = tid + p * 256;
        int row = o >> 2;
        int c16 = o & 3;
        const __half* g = g_Ah + (size_t)(m0 + row) * KTOT + kc + c16 * 8;
        cp16(sbuf + SM_AH + row * 80 + c16 * 16, g);
    }
    {
        int row = tid >> 2;
        int c16 = tid & 3;
        const __half* g = g_Bh + (size_t)(n0 + row) * KTOT + kc + c16 * 8;
        cp16(sbuf + SM_BH + row * 80 + c16 * 16, g);
    }
}

__global__ __launch_bounds__(256, 3) void gemm_mma_kernel() {
    extern __shared__ char smem[];
    uint32_t sb = smem_u32(smem);
    int tid = threadIdx.x;
    int lane = tid & 31;
    int wid = tid >> 5;
    int wm = wid >> 2;          // 0..1
    int wn = wid & 3;           // 0..3
    int m0 = blockIdx.x * 128;
    int n0 = blockIdx.y * 64;
    int sp = blockIdx.z;
    int kb = sp * GKSPL;

    float acc[4][2][4];
#pragma unroll
    for (int mi = 0; mi < 4; mi++)
#pragma unroll
        for (int nj = 0; nj < 2; nj++)
#pragma unroll
            for (int q = 0; q < 4; q++) acc[mi][nj][q] = 0.0f;

    // prologue: prefetch 2 stages deep
    load_chunk(sb + 0 * SM_BUF, m0, n0, kb + 0 * GCHUNK, tid);
    cp_commit();
    load_chunk(sb + 1 * SM_BUF, m0, n0, kb + 1 * GCHUNK, tid);
    cp_commit();

    int lr = lane & 15;
    int lch = (lane >> 4) * 8;
    int stage = 0;

    for (int it = 0; it < GITERS; it++) {
        uint32_t cbuf = sb + stage * SM_BUF;
        cp_wait1();                  // stage `it` complete (<=1 group pending)
        __syncthreads();             // all threads see it; prior reads of reused buffer done

        if (it + 2 < GITERS) {       // issue load for it+2 into the buffer freed at it-1
            int nstage = stage + 2;
            if (nstage >= NSTAGE) nstage -= NSTAGE;
            load_chunk(sb + nstage * SM_BUF, m0, n0, kb + (it + 2) * GCHUNK, tid);
            cp_commit();
        } else {
            cp_commit();             // keep group count in step for cp_wait1 semantics
        }

#pragma unroll
        for (int s = 0; s < 2; s++) {
            uint32_t ah[4][4], bh[2][2];
#pragma unroll
            for (int mi = 0; mi < 4; mi++) {
                uint32_t off = (uint32_t)(wm * 64 + mi * 16 + lr) * 80 + (s * 16 + lch) * 2;
                ldm4(ah[mi], cbuf + SM_AH + off);
            }
            {
                uint32_t off = (uint32_t)(wn * 16 + lr) * 80 + (s * 16 + lch) * 2;
                uint32_t r[4];
                ldm4(r, cbuf + SM_BH + off);
                bh[0][0] = r[0]; bh[0][1] = r[2];
                bh[1][0] = r[1]; bh[1][1] = r[3];
            }
#pragma unroll
            for (int mi = 0; mi < 4; mi++)
#pragma unroll
                for (int nj = 0; nj < 2; nj++)
                    mma16816(acc[mi][nj], ah[mi], bh[nj]);
        }

        stage++;
        if (stage >= NSTAGE) stage = 0;
    }

    float* pB = g_part + (size_t)sp * NB * ND;
    int g = lane >> 2;
    int tq = lane & 3;
#pragma unroll
    for (int mi = 0; mi < 4; mi++) {
#pragma unroll
        for (int nj = 0; nj < 2; nj++) {
            int m = m0 + wm * 64 + mi * 16 + g;
            int n = n0 + wn * 16 + nj * 8 + tq * 2;
            float2 v0 = {acc[mi][nj][0], acc[mi][nj][1]};
            float2 v1 = {acc[mi][nj][2], acc[mi][nj][3]};
            *(float2*)&pB[(size_t)m * ND + n] = v0;
            *(float2*)&pB[(size_t)(m + 8) * ND + n] = v1;
        }
    }
}

// ---------------- K3: deterministic reduce + ReLU (float2 granularity) ----------------
__global__ void reduce_relu_kernel(float* __restrict__ out) {
    int idx = blockIdx.x * 256 + threadIdx.x;      // float2 index, 262144 total
    const float2* p = (const float2*)g_part;
    float2 v[GSPLIT];
#pragma unroll
    for (int sp = 0; sp < GSPLIT; sp++)
        v[sp] = p[(size_t)sp * (NB * ND / 2) + idx];
    float2 s = v[0];
#pragma unroll
    for (int sp = 1; sp < GSPLIT; sp++) { s.x += v[sp].x; s.y += v[sp].y; }
    s.x = s.x > 0.0f ? s.x : 0.0f;
    s.y = s.y > 0.0f ? s.y : 0.0f;
    ((float2*)out)[idx] = s;
}

// ---------------- launch (serial, single stream) ----------------
extern "C" void kernel_launch(void* const* d_in, const int* in_sizes, int n_in,
                              void* d_out, int out_size) {
    const int*   nodes  = nullptr;
    const int*   uniq   = nullptr;
    const float* masks  = nullptr;
    const float* emb    = nullptr;
    const float* weight = nullptr;
    const float* relw   = nullptr;

    for (int i = 0; i < n_in; i++) {
        switch (in_sizes[i]) {
            case NB:           nodes  = (const int*)d_in[i];   break;
            case NU:           uniq   = (const int*)d_in[i];   break;
            case NR * NB * NU: masks  = (const float*)d_in[i]; break;
            case 100000 * ND:  emb    = (const float*)d_in[i]; break;
            case ND * ND:      weight = (const float*)d_in[i]; break;
            case NR * ND * ND: relw   = (const float*)d_in[i]; break;
            default: break;
        }
    }
    float* out = (float*)d_out;

    static int smem_set = 0;
    if (!smem_set) {
        cudaFuncSetAttribute(gemm_mma_kernel, cudaFuncAttributeMaxDynamicSharedMemorySize, GSMEM);
        smem_set = 1;
    }

    combo_kernel<<<MASK_BLKS + 768, 256>>>(masks, emb, uniq, nodes, weight, relw);
    gemm_mma_kernel<<<dim3(NB / 128, ND / 64, GSPLIT), 256, GSMEM>>>();
    reduce_relu_kernel<<<NB * ND / 2 / 256, 256>>>(out);
}